// round 2
// baseline (speedup 1.0000x reference)
#include <cuda_runtime.h>
#include <math.h>

#define VOCAB  32000
#define EMBED  300
#define HIDDEN 1024
#define POL    3
#define BS     64
#define SEQ    512
#define G4H    (4 * HIDDEN)

#define NBLK   128   // persistent CTAs in recurrence (<=148 SMs -> all co-resident)
#define CPB    32    // gate columns per block (8 h-cols x 4 gates)
#define HPB    8     // h columns per block
#define KC     60    // K-chunk for the xU GEMM (300 = 5*60)

// ---------------- scratch (device globals; no allocations allowed) ----------------
__device__ float g_xu[(size_t)SEQ * G4H * BS];   // [s][jp][b]  512 MB
__device__ float g_Vr[(size_t)HIDDEN * G4H];     // [p][k][cc]  16 MB (permuted V)
__device__ float g_Ur[(size_t)EMBED * G4H];      // [e][jp]     4.9 MB (permuted U)
__device__ float g_br[G4H];                      // [jp]        permuted bias
__device__ float g_h[2][HIDDEN * BS];            // k-major: h[buf][hcol][b]
__device__ unsigned g_bar_arrive;
__device__ unsigned g_bar_gen;

// jp <-> original column mapping:
//   jp = p*32 + cc,  cc = g*8 + l,  original j = g*1024 + 8*p + l

// ---------------- prep: permute weights, zero h, reset barrier ----------------
__global__ void prep_kernel(const float* __restrict__ Vi, const float* __restrict__ Vf,
                            const float* __restrict__ Vc, const float* __restrict__ Vo,
                            const float* __restrict__ Ui, const float* __restrict__ Uf,
                            const float* __restrict__ Uc, const float* __restrict__ Uo,
                            const float* __restrict__ bi, const float* __restrict__ bf,
                            const float* __restrict__ bc, const float* __restrict__ bo)
{
    size_t idx0 = (size_t)blockIdx.x * blockDim.x + threadIdx.x;
    size_t stride = (size_t)gridDim.x * blockDim.x;
    if (idx0 == 0) { g_bar_arrive = 0u; g_bar_gen = 0u; }

    // Vr[(p*1024 + k)*32 + cc] = V_g[k][8p + l]
    for (size_t i = idx0; i < (size_t)HIDDEN * G4H; i += stride) {
        int cc = (int)(i & 31);
        size_t t = i >> 5;
        int k = (int)(t & 1023);
        int p = (int)(t >> 10);
        int g = cc >> 3, l = cc & 7;
        int col = 8 * p + l;
        const float* V = (g == 0) ? Vi : (g == 1) ? Vf : (g == 2) ? Vc : Vo;
        g_Vr[i] = V[(size_t)k * HIDDEN + col];
    }
    // Ur[e*4096 + jp] = U_g[e][8p + l]
    for (size_t i = idx0; i < (size_t)EMBED * G4H; i += stride) {
        int jp = (int)(i % G4H);
        size_t e = i / G4H;
        int p = jp >> 5, cc = jp & 31, g = cc >> 3, l = cc & 7;
        int col = 8 * p + l;
        const float* U = (g == 0) ? Ui : (g == 1) ? Uf : (g == 2) ? Uc : Uo;
        g_Ur[i] = U[e * HIDDEN + col];
    }
    for (size_t i = idx0; i < (size_t)G4H; i += stride) {
        int jp = (int)i;
        int p = jp >> 5, cc = jp & 31, g = cc >> 3, l = cc & 7;
        const float* b = (g == 0) ? bi : (g == 1) ? bf : (g == 2) ? bc : bo;
        g_br[i] = b[8 * p + l];
    }
    for (size_t i = idx0; i < (size_t)HIDDEN * BS; i += stride) g_h[0][i] = 0.0f;
}

// ---------------- xU: fused embed-gather GEMM  out[s][jp][b] = x@U + b ----------------
__global__ void __launch_bounds__(256) xu_kernel(const int* __restrict__ text,
                                                 const float* __restrict__ embed)
{
    __shared__ __align__(16) float Ua[KC][68];   // [e][jp-in-tile]
    __shared__ __align__(16) float Xb[KC][68];   // [e][b]
    __shared__ int rows[BS];

    const int s = blockIdx.y;
    const int jpBase = blockIdx.x * 64;
    const int tid = threadIdx.x;

    if (tid < BS) rows[tid] = text[tid * SEQ + s];
    __syncthreads();

    const int tx = tid & 15, ty = tid >> 4;
    const int jp0 = tx * 4, b0 = ty * 4;

    float acc[4][4];
#pragma unroll
    for (int i = 0; i < 4; i++)
#pragma unroll
        for (int j = 0; j < 4; j++) acc[i][j] = 0.0f;

    for (int e0 = 0; e0 < EMBED; e0 += KC) {
        for (int idx = tid; idx < KC * 64; idx += 256) {
            int e = idx >> 6, c = idx & 63;
            Ua[e][c] = g_Ur[(size_t)(e0 + e) * G4H + jpBase + c];
        }
        for (int idx = tid; idx < KC * 64; idx += 256) {
            int b = idx / KC, e = idx - b * KC;
            Xb[e][b] = embed[(size_t)rows[b] * EMBED + e0 + e];
        }
        __syncthreads();
#pragma unroll 4
        for (int e = 0; e < KC; e++) {
            float4 ua = *(const float4*)&Ua[e][jp0];
            float4 xb = *(const float4*)&Xb[e][b0];
            float a[4] = {ua.x, ua.y, ua.z, ua.w};
            float x4[4] = {xb.x, xb.y, xb.z, xb.w};
#pragma unroll
            for (int i = 0; i < 4; i++)
#pragma unroll
                for (int j = 0; j < 4; j++)
                    acc[i][j] = fmaf(a[i], x4[j], acc[i][j]);
        }
        __syncthreads();
    }

#pragma unroll
    for (int i = 0; i < 4; i++) {
        int jp = jpBase + jp0 + i;
        float bias = g_br[jp];
        float4 v = make_float4(acc[i][0] + bias, acc[i][1] + bias,
                               acc[i][2] + bias, acc[i][3] + bias);
        *(float4*)(g_xu + ((size_t)s * G4H + jp) * BS + b0) = v;
    }
}

// ---------------- persistent recurrence ----------------
__global__ void __launch_bounds__(256, 1) rnn_kernel()
{
    __shared__ __align__(16) float hch[128 * BS];     // staged h chunk [kk][b]  32 KB
    __shared__ __align__(16) float gbuf[CPB * 68];    // gate preacts [cc][b]    8.5 KB
    __shared__ float cst[HPB * BS];                   // cell state [l][b]       2 KB

    const int p = blockIdx.x;
    const int tid = threadIdx.x;
    const int cpair = tid & 15;
    const int bq = tid >> 4;
    const int c0 = cpair * 2;
    const int b0 = bq * 4;

    for (int i = tid; i < HPB * BS; i += 256) cst[i] = 0.0f;

    const float* __restrict__ Vrp = g_Vr + (size_t)p * HIDDEN * CPB;

    for (int t = 0; t < SEQ; t++) {
        const float* hsrc = g_h[t & 1];
        float* hdst = g_h[(t + 1) & 1];
        const float* xup = g_xu + ((size_t)t * G4H + p * CPB) * BS;

        // acc starts at xu (bias already folded in)
        float acc[2][4];
#pragma unroll
        for (int i = 0; i < 2; i++) {
            float4 v = __ldcs((const float4*)(xup + (c0 + i) * BS + b0));
            acc[i][0] = v.x; acc[i][1] = v.y; acc[i][2] = v.z; acc[i][3] = v.w;
        }

        // gates += h @ V  (K = 1024, staged in 8 chunks of 128)
        for (int kc = 0; kc < HIDDEN; kc += 128) {
            __syncthreads();
            const float4* hs4 = (const float4*)(hsrc + kc * BS);
            float4* hch4 = (float4*)hch;
#pragma unroll
            for (int i = 0; i < 8; i++)
                hch4[i * 256 + tid] = __ldcs(hs4 + i * 256 + tid);  // stream; keep V in L1
            __syncthreads();
            const float* Vk = Vrp + (size_t)kc * CPB;
#pragma unroll 4
            for (int kk = 0; kk < 128; kk++) {
                float4 hv = *(const float4*)&hch[kk * BS + b0];
                float2 vv = __ldg((const float2*)(Vk + kk * CPB + c0));
                acc[0][0] = fmaf(vv.x, hv.x, acc[0][0]);
                acc[0][1] = fmaf(vv.x, hv.y, acc[0][1]);
                acc[0][2] = fmaf(vv.x, hv.z, acc[0][2]);
                acc[0][3] = fmaf(vv.x, hv.w, acc[0][3]);
                acc[1][0] = fmaf(vv.y, hv.x, acc[1][0]);
                acc[1][1] = fmaf(vv.y, hv.y, acc[1][1]);
                acc[1][2] = fmaf(vv.y, hv.z, acc[1][2]);
                acc[1][3] = fmaf(vv.y, hv.w, acc[1][3]);
            }
        }

#pragma unroll
        for (int i = 0; i < 2; i++)
            *(float4*)&gbuf[(c0 + i) * 68 + b0] =
                make_float4(acc[i][0], acc[i][1], acc[i][2], acc[i][3]);
        __syncthreads();

        // nonlinearity + state update for this block's 8 h-columns
#pragma unroll
        for (int r = 0; r < 2; r++) {
            int idx = tid + r * 256;     // (l, b): l = idx>>6, b = idx&63
            int l = idx >> 6;
            int b = idx & 63;
            float xi = gbuf[l * 68 + b];
            float xf = gbuf[(8 + l) * 68 + b];
            float xg = gbuf[(16 + l) * 68 + b];
            float xo = gbuf[(24 + l) * 68 + b];
            float iv = 1.0f / (1.0f + __expf(-xi));
            float fv = 1.0f / (1.0f + __expf(-xf));
            float gv = tanhf(xg);
            float ov = 1.0f / (1.0f + __expf(-xo));
            float cv = fmaf(fv, cst[idx], iv * gv);
            cst[idx] = cv;
            hdst[(p * HPB + l) * BS + b] = ov * tanhf(cv);
        }
        __syncthreads();

        // ---- grid barrier (monotone generation; reset each launch by prep) ----
        if (tid == 0) {
            __threadfence();
            unsigned target = (unsigned)(t + 1);
            unsigned old = atomicAdd(&g_bar_arrive, 1u);
            if (old == target * NBLK - 1u) {
                atomicAdd(&g_bar_gen, 1u);
            } else {
                while (*((volatile unsigned*)&g_bar_gen) < target) { }
            }
            __threadfence();
        }
        __syncthreads();
    }
}

// ---------------- head: out = h_n @ W_dense + b_dense ----------------
__global__ void head_kernel(const float* __restrict__ W, const float* __restrict__ bd,
                            float* __restrict__ out)
{
    int tid = threadIdx.x;
    if (tid < BS * POL) {
        int b = tid / POL, pp = tid - b * POL;
        float s = bd[pp];
        const float* h = g_h[0];  // after 512 steps, final h lives in buffer 0
        for (int k = 0; k < HIDDEN; k++)
            s = fmaf(h[k * BS + b], W[k * POL + pp], s);
        out[tid] = s;
    }
}

// ---------------- launch ----------------
extern "C" void kernel_launch(void* const* d_in, const int* in_sizes, int n_in,
                              void* d_out, int out_size)
{
    (void)in_sizes; (void)n_in; (void)out_size;
    const int*   text  = (const int*)d_in[0];
    const float* embed = (const float*)d_in[1];
    const float* Ui = (const float*)d_in[2],  *Uf = (const float*)d_in[3];
    const float* Uc = (const float*)d_in[4],  *Uo = (const float*)d_in[5];
    const float* Vi = (const float*)d_in[6],  *Vf = (const float*)d_in[7];
    const float* Vc = (const float*)d_in[8],  *Vo = (const float*)d_in[9];
    const float* bi = (const float*)d_in[10], *bf = (const float*)d_in[11];
    const float* bc = (const float*)d_in[12], *bo = (const float*)d_in[13];
    const float* W  = (const float*)d_in[14], *bd = (const float*)d_in[15];
    float* out = (float*)d_out;

    prep_kernel<<<2048, 256>>>(Vi, Vf, Vc, Vo, Ui, Uf, Uc, Uo, bi, bf, bc, bo);

    dim3 gx(G4H / 64, SEQ);
    xu_kernel<<<gx, 256>>>(text, embed);

    rnn_kernel<<<NBLK, 256>>>();

    head_kernel<<<1, 256>>>(W, bd, out);
}

// round 3
// speedup vs baseline: 2.3563x; 2.3563x over previous
#include <cuda_runtime.h>
#include <math.h>

#define VOCAB  32000
#define EMBED  300
#define HIDDEN 1024
#define POL    3
#define BS     64
#define SEQ    512
#define G4H    (4 * HIDDEN)

#define NBLK   128   // persistent CTAs (<=148 SMs -> co-resident)
#define CPB    32    // gate columns per CTA (8 h-cols x 4 gates)
#define HPB    8
#define KC     60    // K-chunk for xU GEMM

#define HS     132   // hch smem row stride (conflict-free B-frag loads)
#define GS     68    // gate buffer stride
#define PACKF  32768 // floats per CTA in V packs: 128 ks * 2 mt * 32 lanes * 4

// smem layout (floats) for rnn kernel
#define SM_VHI  0
#define SM_HH   32768
#define SM_HL   41216            // 32768 + 64*132
#define SM_GB   49664            // 41216 + 8448
#define SM_CS   51840            // 49664 + 32*68
#define SM_TOT  52352
#define SMEM_BYTES (SM_TOT * 4)  // 209408

// ---------------- device scratch ----------------
__device__ float g_xu[(size_t)SEQ * G4H * BS];       // [s][jp][b]
__device__ float g_Vhi[(size_t)NBLK * PACKF];        // A-fragment-packed tf32(V)
__device__ float g_Vlo[(size_t)NBLK * PACKF];        // A-fragment-packed (V - tf32(V))
__device__ float g_Ur[(size_t)EMBED * G4H];          // permuted U
__device__ float g_br[G4H];                          // permuted bias
__device__ float g_h[2][BS * HIDDEN];                // h[buf][b][k]  (k contiguous)
__device__ unsigned g_bar_arrive;
__device__ unsigned g_bar_gen;

// column mapping: jp = p*32 + cc, cc = g*8 + l, original col j = g*1024 + 8p + l

__device__ __forceinline__ float tf32r(float x) {
    unsigned u;
    asm("cvt.rna.tf32.f32 %0, %1;" : "=r"(u) : "f"(x));
    return __uint_as_float(u);
}

#define MMA_TF32(c, a0,a1,a2,a3, b0,b1)                                        \
    asm volatile("mma.sync.aligned.m16n8k8.row.col.f32.tf32.tf32.f32 "         \
                 "{%0,%1,%2,%3}, {%4,%5,%6,%7}, {%8,%9}, {%0,%1,%2,%3};"       \
                 : "+f"(c[0]), "+f"(c[1]), "+f"(c[2]), "+f"(c[3])              \
                 : "r"(a0), "r"(a1), "r"(a2), "r"(a3), "r"(b0), "r"(b1))

// ---------------- prep: pack weights, zero h, reset barrier ----------------
__global__ void prep_kernel(const float* __restrict__ Vi, const float* __restrict__ Vf,
                            const float* __restrict__ Vc, const float* __restrict__ Vo,
                            const float* __restrict__ Ui, const float* __restrict__ Uf,
                            const float* __restrict__ Uc, const float* __restrict__ Uo,
                            const float* __restrict__ bi, const float* __restrict__ bf,
                            const float* __restrict__ bc, const float* __restrict__ bo)
{
    size_t idx0 = (size_t)blockIdx.x * blockDim.x + threadIdx.x;
    size_t stride = (size_t)gridDim.x * blockDim.x;
    if (idx0 == 0) { g_bar_arrive = 0u; g_bar_gen = 0u; }

    // V packs in mma A-fragment order.
    // index i -> p[21:15] ks[14:8] mt[7] lane[6:2] r[1:0]
    // a-reg r at (row = mt*16 + g8 + (r&1)*8, col k = ks*8 + tig + (r>>1)*4)
    for (size_t i = idx0; i < (size_t)NBLK * PACKF; i += stride) {
        int r    = (int)(i & 3);
        int lane = (int)((i >> 2) & 31);
        int mt   = (int)((i >> 7) & 1);
        int ks   = (int)((i >> 8) & 127);
        int p    = (int)(i >> 15);
        int g8 = lane >> 2, tig = lane & 3;
        int cc = mt * 16 + g8 + (r & 1) * 8;
        int k  = ks * 8 + tig + ((r >> 1) & 1) * 4;
        int g = cc >> 3, l = cc & 7;
        const float* V = (g == 0) ? Vi : (g == 1) ? Vf : (g == 2) ? Vc : Vo;
        float v = V[(size_t)k * HIDDEN + 8 * p + l];
        float hi = tf32r(v);
        g_Vhi[i] = hi;
        g_Vlo[i] = v - hi;
    }
    // Ur[e*4096 + jp] = U_g[e][8p + l]
    for (size_t i = idx0; i < (size_t)EMBED * G4H; i += stride) {
        int jp = (int)(i % G4H);
        size_t e = i / G4H;
        int p = jp >> 5, cc = jp & 31, g = cc >> 3, l = cc & 7;
        const float* U = (g == 0) ? Ui : (g == 1) ? Uf : (g == 2) ? Uc : Uo;
        g_Ur[i] = U[e * HIDDEN + 8 * p + l];
    }
    for (size_t i = idx0; i < (size_t)G4H; i += stride) {
        int jp = (int)i;
        int p = jp >> 5, cc = jp & 31, g = cc >> 3, l = cc & 7;
        const float* b = (g == 0) ? bi : (g == 1) ? bf : (g == 2) ? bc : bo;
        g_br[i] = b[8 * p + l];
    }
    for (size_t i = idx0; i < (size_t)BS * HIDDEN; i += stride) g_h[0][i] = 0.0f;
}

// ---------------- xU: fused embed-gather GEMM  out[s][jp][b] ----------------
__global__ void __launch_bounds__(256) xu_kernel(const int* __restrict__ text,
                                                 const float* __restrict__ embed)
{
    __shared__ __align__(16) float Ua[KC][68];
    __shared__ __align__(16) float Xb[KC][68];
    __shared__ int rows[BS];

    const int s = blockIdx.y;
    const int jpBase = blockIdx.x * 64;
    const int tid = threadIdx.x;

    if (tid < BS) rows[tid] = text[tid * SEQ + s];
    __syncthreads();

    const int tx = tid & 15, ty = tid >> 4;
    const int jp0 = tx * 4, b0 = ty * 4;

    float acc[4][4];
#pragma unroll
    for (int i = 0; i < 4; i++)
#pragma unroll
        for (int j = 0; j < 4; j++) acc[i][j] = 0.0f;

    for (int e0 = 0; e0 < EMBED; e0 += KC) {
        for (int idx = tid; idx < KC * 64; idx += 256) {
            int e = idx >> 6, c = idx & 63;
            Ua[e][c] = g_Ur[(size_t)(e0 + e) * G4H + jpBase + c];
        }
        for (int idx = tid; idx < KC * 64; idx += 256) {
            int b = idx / KC, e = idx - b * KC;
            Xb[e][b] = embed[(size_t)rows[b] * EMBED + e0 + e];
        }
        __syncthreads();
#pragma unroll 4
        for (int e = 0; e < KC; e++) {
            float4 ua = *(const float4*)&Ua[e][jp0];
            float4 xb = *(const float4*)&Xb[e][b0];
            float a[4] = {ua.x, ua.y, ua.z, ua.w};
            float x4[4] = {xb.x, xb.y, xb.z, xb.w};
#pragma unroll
            for (int i = 0; i < 4; i++)
#pragma unroll
                for (int j = 0; j < 4; j++)
                    acc[i][j] = fmaf(a[i], x4[j], acc[i][j]);
        }
        __syncthreads();
    }

#pragma unroll
    for (int i = 0; i < 4; i++) {
        int jp = jpBase + jp0 + i;
        float bias = g_br[jp];
        float4 v = make_float4(acc[i][0] + bias, acc[i][1] + bias,
                               acc[i][2] + bias, acc[i][3] + bias);
        *(float4*)(g_xu + ((size_t)s * G4H + jp) * BS + b0) = v;
    }
}

// ---------------- persistent recurrence (tf32 tensor cores, 3-term split) ----------------
__global__ void __launch_bounds__(256, 1) rnn_kernel()
{
    extern __shared__ __align__(16) float smem[];
    float* Vs = smem + SM_VHI;   // V_hi fragment pack (32768 f)
    float* hh = smem + SM_HH;    // h_hi chunk [b][kk] stride HS
    float* hl = smem + SM_HL;    // h_lo chunk
    float* gb = smem + SM_GB;    // gate preacts [cc][b] stride GS
    float* cs = smem + SM_CS;    // cell state [l][b]

    const int p = blockIdx.x;
    const int tid = threadIdx.x;
    const int lane = tid & 31;
    const int w = tid >> 5;
    const int g8 = lane >> 2, tig = lane & 3;
    const int mt = w & 1;        // cc half  (cc0 = mt*16)
    const int nq = w >> 1;       // b quarter (n base = nq*16)
    const int cc0 = mt * 16;

    // load V_hi pack into smem; zero cell state
    {
        const float4* src = (const float4*)(g_Vhi + (size_t)p * PACKF);
        float4* dst = (float4*)Vs;
        for (int i = tid; i < PACKF / 4; i += 256) dst[i] = __ldg(src + i);
    }
    for (int i = tid; i < HPB * BS; i += 256) cs[i] = 0.0f;
    __syncthreads();

    const float* vhs = Vs + (mt * 32 + lane) * 4;
    const float* vlp = g_Vlo + (size_t)p * PACKF + (mt * 32 + lane) * 4;
    const int rb = (nq * 16 + g8) * HS + tig;   // B-frag row base in hh/hl

    for (int t = 0; t < SEQ; t++) {
        const float* hsrc = g_h[t & 1];
        float* hdst = g_h[(t + 1) & 1];
        const float* xup = g_xu + ((size_t)t * G4H + p * CPB) * BS;

        // init accumulators from xu (bias folded in)
        float c[2][4];
#pragma unroll
        for (int nt = 0; nt < 2; nt++) {
            int bcol = nq * 16 + nt * 8 + 2 * tig;
            float2 v0 = __ldcs((const float2*)(xup + (cc0 + g8) * BS + bcol));
            float2 v1 = __ldcs((const float2*)(xup + (cc0 + g8 + 8) * BS + bcol));
            c[nt][0] = v0.x; c[nt][1] = v0.y; c[nt][2] = v1.x; c[nt][3] = v1.y;
        }

        for (int kc = 0; kc < HIDDEN; kc += 128) {
            __syncthreads();
            // stage h chunk (fp32 from L2), split into tf32 hi + lo
#pragma unroll
            for (int j = 0; j < 8; j++) {
                int i = tid * 4 + j * 1024;
                int b = i >> 7, kk = i & 127;
                float4 hv = __ldcg((const float4*)(hsrc + b * HIDDEN + kc + kk));
                float4 hi4, lo4;
                hi4.x = tf32r(hv.x); lo4.x = hv.x - hi4.x;
                hi4.y = tf32r(hv.y); lo4.y = hv.y - hi4.y;
                hi4.z = tf32r(hv.z); lo4.z = hv.z - hi4.z;
                hi4.w = tf32r(hv.w); lo4.w = hv.w - hi4.w;
                *(float4*)&hh[b * HS + kk] = hi4;
                *(float4*)&hl[b * HS + kk] = lo4;
            }
            __syncthreads();

            const int ksg0 = kc >> 3;
#pragma unroll 4
            for (int ks = 0; ks < 16; ks++) {
                const int ksg = ksg0 + ks;
                float4 ah4 = *(const float4*)(vhs + ksg * 256);
                float4 al4 = __ldg((const float4*)(vlp + ksg * 256));
                unsigned ah0 = __float_as_uint(ah4.x), ah1 = __float_as_uint(ah4.y);
                unsigned ah2 = __float_as_uint(ah4.z), ah3 = __float_as_uint(ah4.w);
                unsigned al0 = __float_as_uint(al4.x), al1 = __float_as_uint(al4.y);
                unsigned al2 = __float_as_uint(al4.z), al3 = __float_as_uint(al4.w);
                const int kb = ks * 8;
#pragma unroll
                for (int nt = 0; nt < 2; nt++) {
                    int row = rb + nt * 8 * HS + kb;
                    unsigned bh0 = __float_as_uint(hh[row]);
                    unsigned bh1 = __float_as_uint(hh[row + 4]);
                    unsigned bl0 = __float_as_uint(hl[row]);
                    unsigned bl1 = __float_as_uint(hl[row + 4]);
                    MMA_TF32(c[nt], ah0, ah1, ah2, ah3, bh0, bh1);  // h_hi * V_hi
                    MMA_TF32(c[nt], ah0, ah1, ah2, ah3, bl0, bl1);  // h_lo * V_hi
                    MMA_TF32(c[nt], al0, al1, al2, al3, bh0, bh1);  // h_hi * V_lo
                }
            }
        }

        // write gate preacts to smem
#pragma unroll
        for (int nt = 0; nt < 2; nt++) {
            int col = nq * 16 + nt * 8 + 2 * tig;
            *(float2*)&gb[(cc0 + g8) * GS + col] = make_float2(c[nt][0], c[nt][1]);
            *(float2*)&gb[(cc0 + g8 + 8) * GS + col] = make_float2(c[nt][2], c[nt][3]);
        }
        __syncthreads();

        // nonlinearity + state update (8 h-cols x 64 b)
#pragma unroll
        for (int r = 0; r < 2; r++) {
            int idx = tid + r * 256;
            int l = idx >> 6;
            int b = idx & 63;
            float xi = gb[l * GS + b];
            float xf = gb[(8 + l) * GS + b];
            float xg = gb[(16 + l) * GS + b];
            float xo = gb[(24 + l) * GS + b];
            float iv = 1.0f / (1.0f + __expf(-xi));
            float fv = 1.0f / (1.0f + __expf(-xf));
            float gv = tanhf(xg);
            float ov = 1.0f / (1.0f + __expf(-xo));
            float cv = fmaf(fv, cs[idx], iv * gv);
            cs[idx] = cv;
            hdst[b * HIDDEN + 8 * p + l] = ov * tanhf(cv);
        }
        __syncthreads();

        // grid barrier (monotone generation; reset each launch by prep)
        if (tid == 0) {
            __threadfence();
            unsigned target = (unsigned)(t + 1);
            unsigned old = atomicAdd(&g_bar_arrive, 1u);
            if (old == target * NBLK - 1u) {
                atomicAdd(&g_bar_gen, 1u);
            } else {
                while (*((volatile unsigned*)&g_bar_gen) < target) { }
            }
            __threadfence();
        }
        __syncthreads();
    }
}

// ---------------- head: out = h_n @ W_dense + b_dense (warp per output) ----------------
__global__ void head_kernel(const float* __restrict__ W, const float* __restrict__ bd,
                            float* __restrict__ out)
{
    int wg = (blockIdx.x * blockDim.x + threadIdx.x) >> 5;
    int lane = threadIdx.x & 31;
    if (wg >= BS * POL) return;
    int b = wg / POL, pp = wg - b * POL;
    const float* h = g_h[0] + (size_t)b * HIDDEN;   // final h after 512 steps
    float s = 0.0f;
    for (int k = lane; k < HIDDEN; k += 32)
        s = fmaf(h[k], W[k * POL + pp], s);
#pragma unroll
    for (int o = 16; o; o >>= 1) s += __shfl_xor_sync(0xFFFFFFFFu, s, o);
    if (lane == 0) out[wg] = s + bd[pp];
}

// ---------------- launch ----------------
extern "C" void kernel_launch(void* const* d_in, const int* in_sizes, int n_in,
                              void* d_out, int out_size)
{
    (void)in_sizes; (void)n_in; (void)out_size;
    const int*   text  = (const int*)d_in[0];
    const float* embed = (const float*)d_in[1];
    const float* Ui = (const float*)d_in[2],  *Uf = (const float*)d_in[3];
    const float* Uc = (const float*)d_in[4],  *Uo = (const float*)d_in[5];
    const float* Vi = (const float*)d_in[6],  *Vf = (const float*)d_in[7];
    const float* Vc = (const float*)d_in[8],  *Vo = (const float*)d_in[9];
    const float* bi = (const float*)d_in[10], *bf = (const float*)d_in[11];
    const float* bc = (const float*)d_in[12], *bo = (const float*)d_in[13];
    const float* W  = (const float*)d_in[14], *bd = (const float*)d_in[15];
    float* out = (float*)d_out;

    cudaFuncSetAttribute(rnn_kernel, cudaFuncAttributeMaxDynamicSharedMemorySize,
                         SMEM_BYTES);

    prep_kernel<<<2048, 256>>>(Vi, Vf, Vc, Vo, Ui, Uf, Uc, Uo, bi, bf, bc, bo);

    dim3 gx(G4H / 64, SEQ);
    xu_kernel<<<gx, 256>>>(text, embed);

    rnn_kernel<<<NBLK, 256, SMEM_BYTES>>>();

    head_kernel<<<24, 256>>>(W, bd, out);
}

// round 4
// speedup vs baseline: 3.3225x; 1.4100x over previous
#include <cuda_runtime.h>
#include <cuda_fp16.h>
#include <math.h>

#define VOCAB  32000
#define EMBED  300
#define HIDDEN 1024
#define POL    3
#define BS     64
#define SEQ    512
#define G4H    (4 * HIDDEN)

#define NBLK   128     // persistent CTAs
#define CPB    32      // gate cols per CTA
#define HPB    8
#define SK     136     // staged h row stride (halves) -> conflict-free B loads
#define GS     68      // gate buffer stride (floats)
#define PACKV  16384   // uint32 per CTA in V packs (128 tiles * 32 lanes * 4 regs)

#define SKX    312     // xu staged x row stride (halves)
#define KS_XU  19      // ceil(304/16)
#define PACKU  9728    // uint32 per jpTile in U packs (19*4*32*4)

#define INV2048 4.8828125e-4f

// ---- rnn smem offsets (bytes) ----
#define R_VH   0            // 65536
#define R_VL   65536        // 65536
#define R_HH0  131072       // 17408 (64*SK*2)
#define R_HH1  148480
#define R_HL0  165888
#define R_HL1  183296
#define R_GB   200704       // 8704 (32*GS*4)
#define R_CS   209408       // 2048
#define R_HST  211456       // 2048 (hh 1024 | hl 1024)
#define R_TOT  213504

// ---- xu smem offsets (bytes) ----
#define X_UH   0            // 38912 (PACKU*4)
#define X_UL   38912
#define X_XH   77824        // 39936 (64*SKX*2)
#define X_XL   117760
#define X_ROWS 157696       // 256 (int rows[64])
#define X_TOT  157952

// ---------------- device scratch ----------------
__device__ float    g_xu[(size_t)SEQ * G4H * BS];       // [s][jp][b] fp32
__device__ unsigned g_Vh[(size_t)NBLK * PACKV];         // A-frag packed fp16x2
__device__ unsigned g_Vl[(size_t)NBLK * PACKV];         // lo parts * 2048
__device__ unsigned g_Uh[(size_t)64 * PACKU];
__device__ unsigned g_Ul[(size_t)64 * PACKU];
__device__ float    g_br[G4H];
__device__ __half   g_hh[2][BS * HIDDEN];               // h hi fp16 [buf][b][k]
__device__ __half   g_hl[2][BS * HIDDEN];               // (h-hi)*2048 fp16
__device__ unsigned g_bar_arrive;
__device__ unsigned g_bar_gen;

__device__ __forceinline__ unsigned pack2(__half a, __half b) {
    return (unsigned)__half_as_ushort(a) | ((unsigned)__half_as_ushort(b) << 16);
}
__device__ __forceinline__ void split16(float v, __half& hi, __half& lo) {
    hi = __float2half_rn(v);
    lo = __float2half_rn((v - __half2float(hi)) * 2048.0f);
}
__device__ __forceinline__ void cp16(unsigned dst, const void* src) {
    asm volatile("cp.async.cg.shared.global [%0], [%1], 16;" :: "r"(dst), "l"(src));
}
#define CP_COMMIT() asm volatile("cp.async.commit_group;")
#define CP_WAIT1()  asm volatile("cp.async.wait_group 1;")
#define CP_WAIT0()  asm volatile("cp.async.wait_group 0;")

#define MMA_F16(c, a, b0, b1)                                                  \
    asm volatile("mma.sync.aligned.m16n8k16.row.col.f32.f16.f16.f32 "          \
                 "{%0,%1,%2,%3}, {%4,%5,%6,%7}, {%8,%9}, {%0,%1,%2,%3};"       \
                 : "+f"(c[0]), "+f"(c[1]), "+f"(c[2]), "+f"(c[3])              \
                 : "r"(a.x), "r"(a.y), "r"(a.z), "r"(a.w), "r"(b0), "r"(b1))

// ---------------- prep: build fp16 fragment packs, zero h, reset barrier ----------------
__global__ void prep_kernel(const float* __restrict__ Vi, const float* __restrict__ Vf,
                            const float* __restrict__ Vc, const float* __restrict__ Vo,
                            const float* __restrict__ Ui, const float* __restrict__ Uf,
                            const float* __restrict__ Uc, const float* __restrict__ Uo,
                            const float* __restrict__ bi, const float* __restrict__ bf,
                            const float* __restrict__ bc, const float* __restrict__ bo)
{
    size_t idx0 = (size_t)blockIdx.x * blockDim.x + threadIdx.x;
    size_t stride = (size_t)gridDim.x * blockDim.x;
    if (idx0 == 0) { g_bar_arrive = 0u; g_bar_gen = 0u; }

    // V packs: flat i = ((p*128 + tile)*32 + lane)*4 + r,  tile = ks*2 + mt
    for (size_t i = idx0; i < (size_t)NBLK * PACKV; i += stride) {
        int r    = (int)(i & 3);
        int lane = (int)((i >> 2) & 31);
        int tile = (int)((i >> 7) & 127);
        int p    = (int)(i >> 14);
        int mt = tile & 1, ks = tile >> 1;
        int g8 = lane >> 2, tig = lane & 3;
        int cc = mt * 16 + g8 + (r & 1) * 8;
        int k0 = ks * 16 + tig * 2 + ((r >> 1) & 1) * 8;
        int g = cc >> 3, l = cc & 7;
        const float* V = (g == 0) ? Vi : (g == 1) ? Vf : (g == 2) ? Vc : Vo;
        float v0 = V[(size_t)k0 * HIDDEN + 8 * p + l];
        float v1 = V[(size_t)(k0 + 1) * HIDDEN + 8 * p + l];
        __half h0, l0, h1, l1;
        split16(v0, h0, l0); split16(v1, h1, l1);
        g_Vh[i] = pack2(h0, h1);
        g_Vl[i] = pack2(l0, l1);
    }

    // U packs: flat i = (((jpT*19 + ks)*4 + mtq)*32 + lane)*4 + r
    for (size_t i = idx0; i < (size_t)64 * PACKU; i += stride) {
        int r    = (int)(i & 3);
        int lane = (int)((i >> 2) & 31);
        int mtq  = (int)((i >> 7) & 3);
        int rest = (int)(i >> 9);
        int ks = rest % KS_XU, jpT = rest / KS_XU;
        int g8 = lane >> 2, tig = lane & 3;
        int jp = jpT * 64 + mtq * 16 + g8 + (r & 1) * 8;
        int e0 = ks * 16 + tig * 2 + ((r >> 1) & 1) * 8;
        int g = (jp >> 3) & 3, l = jp & 7, p = jp >> 5;
        const float* U = (g == 0) ? Ui : (g == 1) ? Uf : (g == 2) ? Uc : Uo;
        float v0 = (e0     < EMBED) ? U[(size_t)e0 * HIDDEN + 8 * p + l] : 0.0f;
        float v1 = (e0 + 1 < EMBED) ? U[(size_t)(e0 + 1) * HIDDEN + 8 * p + l] : 0.0f;
        __half h0, l0, h1, l1;
        split16(v0, h0, l0); split16(v1, h1, l1);
        g_Uh[i] = pack2(h0, h1);
        g_Ul[i] = pack2(l0, l1);
    }

    for (size_t i = idx0; i < (size_t)G4H; i += stride) {
        int jp = (int)i;
        int p = jp >> 5, cc = jp & 31, g = cc >> 3, l = cc & 7;
        const float* b = (g == 0) ? bi : (g == 1) ? bf : (g == 2) ? bc : bo;
        g_br[i] = b[8 * p + l];
    }
    for (size_t i = idx0; i < (size_t)BS * HIDDEN; i += stride) {
        g_hh[0][i] = __ushort_as_half((unsigned short)0);
        g_hl[0][i] = __ushort_as_half((unsigned short)0);
    }
}

// ---------------- xu: fused embed-gather fp16 mma GEMM  out[s][jp][b] ----------------
__global__ void __launch_bounds__(512) xu_kernel(const int* __restrict__ text,
                                                 const float* __restrict__ embed)
{
    extern __shared__ __align__(16) char sm[];
    unsigned* UH = (unsigned*)(sm + X_UH);
    unsigned* UL = (unsigned*)(sm + X_UL);
    __half*   XH = (__half*)(sm + X_XH);
    __half*   XL = (__half*)(sm + X_XL);
    int*      rows = (int*)(sm + X_ROWS);

    const int jpT = blockIdx.x;
    const int s   = blockIdx.y;
    const int tid = threadIdx.x;

    if (tid < BS) rows[tid] = text[tid * SEQ + s];

    // load U packs for this jpTile
    {
        const uint4* sh = (const uint4*)(g_Uh + (size_t)jpT * PACKU);
        const uint4* sl = (const uint4*)(g_Ul + (size_t)jpT * PACKU);
        uint4* dh = (uint4*)UH;
        uint4* dl = (uint4*)UL;
        for (int i = tid; i < PACKU / 4; i += 512) { dh[i] = __ldg(sh + i); dl[i] = __ldg(sl + i); }
    }
    __syncthreads();   // rows ready

    // stage x: gather + split (pad 300..311 with zeros)
    for (int idx = tid; idx < BS * SKX; idx += 512) {
        int b = idx / SKX, e = idx - b * SKX;
        float v = (e < EMBED) ? __ldg(embed + (size_t)rows[b] * EMBED + e) : 0.0f;
        __half hi, lo; split16(v, hi, lo);
        XH[b * SKX + e] = hi;
        XL[b * SKX + e] = lo;
    }
    __syncthreads();

    const int w = tid >> 5, lane = tid & 31;
    const int mtq = w & 3, btile = w >> 2;
    const int g8 = lane >> 2, tig = lane & 3;

    float c1[2][4], c2[2][4];
#pragma unroll
    for (int nt = 0; nt < 2; nt++)
#pragma unroll
        for (int j = 0; j < 4; j++) { c1[nt][j] = 0.0f; c2[nt][j] = 0.0f; }

    const int hbase = (btile * 16 + g8) * SKX + tig * 2;   // halves
#pragma unroll 2
    for (int ks = 0; ks < KS_XU; ks++) {
        int tile = ks * 4 + mtq;
        uint4 ah = *(const uint4*)((const char*)UH + tile * 512 + lane * 16);
        uint4 al = *(const uint4*)((const char*)UL + tile * 512 + lane * 16);
#pragma unroll
        for (int nt = 0; nt < 2; nt++) {
            int hb = hbase + nt * 8 * SKX + ks * 16;
            unsigned bh0 = *(const unsigned*)(XH + hb);
            unsigned bh1 = *(const unsigned*)(XH + hb + 8);
            unsigned bl0 = *(const unsigned*)(XL + hb);
            unsigned bl1 = *(const unsigned*)(XL + hb + 8);
            MMA_F16(c1[nt], ah, bh0, bh1);
            MMA_F16(c2[nt], ah, bl0, bl1);
            MMA_F16(c2[nt], al, bh0, bh1);
        }
    }

    // epilogue: out = c1 + c2/2048 + bias
    const int jp0 = jpT * 64 + mtq * 16 + g8;
#pragma unroll
    for (int nt = 0; nt < 2; nt++) {
        int col = btile * 16 + nt * 8 + tig * 2;
        float b0 = g_br[jp0], b1 = g_br[jp0 + 8];
        float2 v0 = make_float2(c1[nt][0] + INV2048 * c2[nt][0] + b0,
                                c1[nt][1] + INV2048 * c2[nt][1] + b0);
        float2 v1 = make_float2(c1[nt][2] + INV2048 * c2[nt][2] + b1,
                                c1[nt][3] + INV2048 * c2[nt][3] + b1);
        *(float2*)(g_xu + ((size_t)s * G4H + jp0) * BS + col) = v0;
        *(float2*)(g_xu + ((size_t)s * G4H + jp0 + 8) * BS + col) = v1;
    }
}

// ---------------- persistent recurrence (fp16 mma, 3-term, cp.async pipeline) ----------------
__global__ void __launch_bounds__(256, 1) rnn_kernel()
{
    extern __shared__ __align__(16) char sm[];
    float* gb = (float*)(sm + R_GB);
    float* cs = (float*)(sm + R_CS);
    __half* hstH = (__half*)(sm + R_HST);
    __half* hstL = (__half*)(sm + R_HST + 1024);

    const int p = blockIdx.x;
    const int tid = threadIdx.x;
    const int lane = tid & 31;
    const int w = tid >> 5;
    const int g8 = lane >> 2, tig = lane & 3;
    const int mt = w & 1;
    const int nq = w >> 1;
    const int cc0 = mt * 16;

    // load V packs to smem; zero cell state
    {
        const uint4* sh = (const uint4*)(g_Vh + (size_t)p * PACKV);
        const uint4* sl = (const uint4*)(g_Vl + (size_t)p * PACKV);
        uint4* dh = (uint4*)(sm + R_VH);
        uint4* dl = (uint4*)(sm + R_VL);
        for (int i = tid; i < PACKV / 4; i += 256) { dh[i] = __ldg(sh + i); dl[i] = __ldg(sl + i); }
    }
    for (int i = tid; i < HPB * BS; i += 256) cs[i] = 0.0f;
    __syncthreads();

    const unsigned shH0 = (unsigned)__cvta_generic_to_shared(sm + R_HH0);
    const unsigned shL0 = (unsigned)__cvta_generic_to_shared(sm + R_HL0);
    const int hbase = ((nq * 16 + g8) * SK + tig * 2) * 2;   // bytes into staged buf

    for (int t = 0; t < SEQ; t++) {
        const int hbuf = t & 1;
        const __half* srcH = g_hh[hbuf];
        const __half* srcL = g_hl[hbuf];
        const float* xup = g_xu + ((size_t)t * G4H + p * CPB) * BS;

        // issue chunk 0 into staging buf 0
        {
#pragma unroll
            for (int j = 0; j < 4; j++) {
                int idx = tid + j * 256;           // 1024 segs: b = idx>>4, seg = idx&15
                int b = idx >> 4, seg = idx & 15;
                unsigned doff = (unsigned)(b * SK + seg * 8) * 2;
                int soff = b * HIDDEN + seg * 8;
                cp16(shH0 + doff, srcH + soff);
                cp16(shL0 + doff, srcL + soff);
            }
            CP_COMMIT();
        }

        // accumulators from xu
        float c1[2][4], c2[2][4];
#pragma unroll
        for (int nt = 0; nt < 2; nt++) {
            int bcol = nq * 16 + nt * 8 + 2 * tig;
            float2 v0 = __ldg((const float2*)(xup + (cc0 + g8) * BS + bcol));
            float2 v1 = __ldg((const float2*)(xup + (cc0 + g8 + 8) * BS + bcol));
            c1[nt][0] = v0.x; c1[nt][1] = v0.y; c1[nt][2] = v1.x; c1[nt][3] = v1.y;
            c2[nt][0] = 0.0f; c2[nt][1] = 0.0f; c2[nt][2] = 0.0f; c2[nt][3] = 0.0f;
        }

        for (int kci = 0; kci < 8; kci++) {
            __syncthreads();   // everyone done reading the buffer we are about to overwrite
            if (kci + 1 < 8) {
                int nb = (kci + 1) & 1;
                unsigned dH = (nb ? (unsigned)__cvta_generic_to_shared(sm + R_HH1) : shH0);
                unsigned dL = (nb ? (unsigned)__cvta_generic_to_shared(sm + R_HL1) : shL0);
                int kc = (kci + 1) * 128;
#pragma unroll
                for (int j = 0; j < 4; j++) {
                    int idx = tid + j * 256;
                    int b = idx >> 4, seg = idx & 15;
                    unsigned doff = (unsigned)(b * SK + seg * 8) * 2;
                    int soff = b * HIDDEN + kc + seg * 8;
                    cp16(dH + doff, srcH + soff);
                    cp16(dL + doff, srcL + soff);
                }
                CP_COMMIT();
                CP_WAIT1();
            } else {
                CP_WAIT0();
            }
            __syncthreads();   // chunk kci visible

            const char* bufH = sm + (((kci & 1) == 0) ? R_HH0 : R_HH1);
            const char* bufL = sm + (((kci & 1) == 0) ? R_HL0 : R_HL1);
#pragma unroll
            for (int ksl = 0; ksl < 8; ksl++) {
                int tile = (kci * 8 + ksl) * 2 + mt;
                uint4 ah = *(const uint4*)(sm + R_VH + tile * 512 + lane * 16);
                uint4 al = *(const uint4*)(sm + R_VL + tile * 512 + lane * 16);
#pragma unroll
                for (int nt = 0; nt < 2; nt++) {
                    int hb = hbase + nt * 8 * SK * 2 + ksl * 32;
                    unsigned bh0 = *(const unsigned*)(bufH + hb);
                    unsigned bh1 = *(const unsigned*)(bufH + hb + 16);
                    unsigned bl0 = *(const unsigned*)(bufL + hb);
                    unsigned bl1 = *(const unsigned*)(bufL + hb + 16);
                    MMA_F16(c1[nt], ah, bh0, bh1);
                    MMA_F16(c2[nt], ah, bl0, bl1);
                    MMA_F16(c2[nt], al, bh0, bh1);
                }
            }
        }

        // combine + write gate preacts
#pragma unroll
        for (int nt = 0; nt < 2; nt++) {
            int col = nq * 16 + nt * 8 + 2 * tig;
            float v0 = c1[nt][0] + INV2048 * c2[nt][0];
            float v1 = c1[nt][1] + INV2048 * c2[nt][1];
            float v2 = c1[nt][2] + INV2048 * c2[nt][2];
            float v3 = c1[nt][3] + INV2048 * c2[nt][3];
            *(float2*)&gb[(cc0 + g8) * GS + col] = make_float2(v0, v1);
            *(float2*)&gb[(cc0 + g8 + 8) * GS + col] = make_float2(v2, v3);
        }
        __syncthreads();

        // nonlinearity + state update; produce fp16 hi/lo into hstage
#pragma unroll
        for (int r = 0; r < 2; r++) {
            int idx = tid + r * 256;
            int l = idx >> 6;
            int b = idx & 63;
            float xi = gb[l * GS + b];
            float xf = gb[(8 + l) * GS + b];
            float xg = gb[(16 + l) * GS + b];
            float xo = gb[(24 + l) * GS + b];
            float iv = 1.0f / (1.0f + __expf(-xi));
            float fv = 1.0f / (1.0f + __expf(-xf));
            float gv = tanhf(xg);
            float ov = 1.0f / (1.0f + __expf(-xo));
            float cv = fmaf(fv, cs[idx], iv * gv);
            cs[idx] = cv;
            float hv = ov * tanhf(cv);
            __half hi, lo; split16(hv, hi, lo);
            hstH[b * 8 + l] = hi;
            hstL[b * 8 + l] = lo;
        }
        __syncthreads();

        // vectorized h store: 16B per (b, array)
        {
            int obuf = (t + 1) & 1;
            if (tid < 64) {
                uint4 v = *(const uint4*)(hstH + tid * 8);
                *(uint4*)(&g_hh[obuf][tid * HIDDEN + 8 * p]) = v;
            } else if (tid < 128) {
                int b = tid - 64;
                uint4 v = *(const uint4*)(hstL + b * 8);
                *(uint4*)(&g_hl[obuf][b * HIDDEN + 8 * p]) = v;
            }
        }
        __syncthreads();

        // grid barrier (monotone generation)
        if (tid == 0) {
            __threadfence();
            unsigned target = (unsigned)(t + 1);
            unsigned old = atomicAdd(&g_bar_arrive, 1u);
            if (old == target * NBLK - 1u) {
                atomicAdd(&g_bar_gen, 1u);
            } else {
                while (*((volatile unsigned*)&g_bar_gen) < target) { }
            }
            __threadfence();
        }
        __syncthreads();
    }
}

// ---------------- head ----------------
__global__ void head_kernel(const float* __restrict__ W, const float* __restrict__ bd,
                            float* __restrict__ out)
{
    int wg = (blockIdx.x * blockDim.x + threadIdx.x) >> 5;
    int lane = threadIdx.x & 31;
    if (wg >= BS * POL) return;
    int b = wg / POL, pp = wg - b * POL;
    const __half* hh = g_hh[0] + (size_t)b * HIDDEN;   // final h in buf 0
    const __half* hl = g_hl[0] + (size_t)b * HIDDEN;
    float s = 0.0f;
    for (int k = lane; k < HIDDEN; k += 32) {
        float h = __half2float(hh[k]) + INV2048 * __half2float(hl[k]);
        s = fmaf(h, W[k * POL + pp], s);
    }
#pragma unroll
    for (int o = 16; o; o >>= 1) s += __shfl_xor_sync(0xFFFFFFFFu, s, o);
    if (lane == 0) out[wg] = s + bd[pp];
}

// ---------------- launch ----------------
extern "C" void kernel_launch(void* const* d_in, const int* in_sizes, int n_in,
                              void* d_out, int out_size)
{
    (void)in_sizes; (void)n_in; (void)out_size;
    const int*   text  = (const int*)d_in[0];
    const float* embed = (const float*)d_in[1];
    const float* Ui = (const float*)d_in[2],  *Uf = (const float*)d_in[3];
    const float* Uc = (const float*)d_in[4],  *Uo = (const float*)d_in[5];
    const float* Vi = (const float*)d_in[6],  *Vf = (const float*)d_in[7];
    const float* Vc = (const float*)d_in[8],  *Vo = (const float*)d_in[9];
    const float* bi = (const float*)d_in[10], *bf = (const float*)d_in[11];
    const float* bc = (const float*)d_in[12], *bo = (const float*)d_in[13];
    const float* W  = (const float*)d_in[14], *bd = (const float*)d_in[15];
    float* out = (float*)d_out;

    cudaFuncSetAttribute(rnn_kernel, cudaFuncAttributeMaxDynamicSharedMemorySize, R_TOT);
    cudaFuncSetAttribute(xu_kernel, cudaFuncAttributeMaxDynamicSharedMemorySize, X_TOT);

    prep_kernel<<<2048, 256>>>(Vi, Vf, Vc, Vo, Ui, Uf, Uc, Uo, bi, bf, bc, bo);

    dim3 gx(G4H / 64, SEQ);
    xu_kernel<<<gx, 512, X_TOT>>>(text, embed);

    rnn_kernel<<<NBLK, 256, R_TOT>>>();

    head_kernel<<<24, 256>>>(W, bd, out);
}

// round 5
// speedup vs baseline: 3.4098x; 1.0263x over previous
#include <cuda_runtime.h>
#include <cuda_fp16.h>
#include <math.h>

#define VOCAB  32000
#define EMBED  300
#define HIDDEN 1024
#define POL    3
#define BS     64
#define SEQ    512
#define G4H    (4 * HIDDEN)

#define NBLK   128     // persistent CTAs
#define CPB    32      // gate cols per CTA
#define HPB    8
#define SK     136     // staged h row stride (halves)
#define GS     68      // gate buffer stride (floats)
#define PACKV  16384   // uint32 per CTA in V packs

#define SKX    312     // xu staged x row stride (halves)
#define KS_XU  19      // ceil(304/16)
#define PACKU  9728    // uint32 per jpTile in U packs
#define SBATCH 8       // seq positions per xu CTA

#define INV2048 4.8828125e-4f

// ---- rnn smem offsets (bytes) ----
#define R_VH   0
#define R_VL   65536
#define R_HH0  131072
#define R_HH1  148480
#define R_HL0  165888
#define R_HL1  183296
#define R_GB   200704
#define R_CS   209408
#define R_HST  211456
#define R_TOT  213504

// ---- xu smem offsets (bytes) ----
#define X_UH   0
#define X_UL   38912
#define X_XH   77824
#define X_XL   117760
#define X_ROWS 157696
#define X_TOT  157952

// ---------------- device scratch ----------------
__device__ float    g_xu[(size_t)SEQ * G4H * BS];       // [s][jp][b] fp32
__device__ unsigned g_Vh[(size_t)NBLK * PACKV];
__device__ unsigned g_Vl[(size_t)NBLK * PACKV];
__device__ unsigned g_Uh[(size_t)64 * PACKU];
__device__ unsigned g_Ul[(size_t)64 * PACKU];
__device__ float    g_br[G4H];
__device__ __half   g_hh[2][BS * HIDDEN];               // h hi fp16 [buf][b][k]
__device__ __half   g_hl[2][BS * HIDDEN];               // (h-hi)*2048 fp16
__device__ unsigned g_flags[NBLK * 32];                 // 128B-padded arrival flags

__device__ __forceinline__ unsigned pack2(__half a, __half b) {
    return (unsigned)__half_as_ushort(a) | ((unsigned)__half_as_ushort(b) << 16);
}
__device__ __forceinline__ void split16(float v, __half& hi, __half& lo) {
    hi = __float2half_rn(v);
    lo = __float2half_rn((v - __half2float(hi)) * 2048.0f);
}
__device__ __forceinline__ void cp16(unsigned dst, const void* src) {
    asm volatile("cp.async.cg.shared.global [%0], [%1], 16;" :: "r"(dst), "l"(src));
}
#define CP_COMMIT() asm volatile("cp.async.commit_group;")
#define CP_WAIT1()  asm volatile("cp.async.wait_group 1;")
#define CP_WAIT0()  asm volatile("cp.async.wait_group 0;")

#define MMA_F16(c, a, b0, b1)                                                  \
    asm volatile("mma.sync.aligned.m16n8k16.row.col.f32.f16.f16.f32 "          \
                 "{%0,%1,%2,%3}, {%4,%5,%6,%7}, {%8,%9}, {%0,%1,%2,%3};"       \
                 : "+f"(c[0]), "+f"(c[1]), "+f"(c[2]), "+f"(c[3])              \
                 : "r"(a.x), "r"(a.y), "r"(a.z), "r"(a.w), "r"(b0), "r"(b1))

// ---------------- dummies: align ncu -s 5 onto rnn_kernel ----------------
__global__ void dummy_kernel() {}

// ---------------- prep ----------------
__global__ void prep_kernel(const float* __restrict__ Vi, const float* __restrict__ Vf,
                            const float* __restrict__ Vc, const float* __restrict__ Vo,
                            const float* __restrict__ Ui, const float* __restrict__ Uf,
                            const float* __restrict__ Uc, const float* __restrict__ Uo,
                            const float* __restrict__ bi, const float* __restrict__ bf,
                            const float* __restrict__ bc, const float* __restrict__ bo)
{
    size_t idx0 = (size_t)blockIdx.x * blockDim.x + threadIdx.x;
    size_t stride = (size_t)gridDim.x * blockDim.x;

    for (size_t i = idx0; i < (size_t)NBLK * 32; i += stride) g_flags[i] = 0u;

    // V packs: flat i = ((p*128 + tile)*32 + lane)*4 + r,  tile = ks*2 + mt
    for (size_t i = idx0; i < (size_t)NBLK * PACKV; i += stride) {
        int r    = (int)(i & 3);
        int lane = (int)((i >> 2) & 31);
        int tile = (int)((i >> 7) & 127);
        int p    = (int)(i >> 14);
        int mt = tile & 1, ks = tile >> 1;
        int g8 = lane >> 2, tig = lane & 3;
        int cc = mt * 16 + g8 + (r & 1) * 8;
        int k0 = ks * 16 + tig * 2 + ((r >> 1) & 1) * 8;
        int g = cc >> 3, l = cc & 7;
        const float* V = (g == 0) ? Vi : (g == 1) ? Vf : (g == 2) ? Vc : Vo;
        float v0 = V[(size_t)k0 * HIDDEN + 8 * p + l];
        float v1 = V[(size_t)(k0 + 1) * HIDDEN + 8 * p + l];
        __half h0, l0, h1, l1;
        split16(v0, h0, l0); split16(v1, h1, l1);
        g_Vh[i] = pack2(h0, h1);
        g_Vl[i] = pack2(l0, l1);
    }

    // U packs: flat i = (((jpT*19 + ks)*4 + mtq)*32 + lane)*4 + r
    for (size_t i = idx0; i < (size_t)64 * PACKU; i += stride) {
        int r    = (int)(i & 3);
        int lane = (int)((i >> 2) & 31);
        int mtq  = (int)((i >> 7) & 3);
        int rest = (int)(i >> 9);
        int ks = rest % KS_XU, jpT = rest / KS_XU;
        int g8 = lane >> 2, tig = lane & 3;
        int jp = jpT * 64 + mtq * 16 + g8 + (r & 1) * 8;
        int e0 = ks * 16 + tig * 2 + ((r >> 1) & 1) * 8;
        int g = (jp >> 3) & 3, l = jp & 7, p = jp >> 5;
        const float* U = (g == 0) ? Ui : (g == 1) ? Uf : (g == 2) ? Uc : Uo;
        float v0 = (e0     < EMBED) ? U[(size_t)e0 * HIDDEN + 8 * p + l] : 0.0f;
        float v1 = (e0 + 1 < EMBED) ? U[(size_t)(e0 + 1) * HIDDEN + 8 * p + l] : 0.0f;
        __half h0, l0, h1, l1;
        split16(v0, h0, l0); split16(v1, h1, l1);
        g_Uh[i] = pack2(h0, h1);
        g_Ul[i] = pack2(l0, l1);
    }

    for (size_t i = idx0; i < (size_t)G4H; i += stride) {
        int jp = (int)i;
        int p = jp >> 5, cc = jp & 31, g = cc >> 3, l = cc & 7;
        const float* b = (g == 0) ? bi : (g == 1) ? bf : (g == 2) ? bc : bo;
        g_br[i] = b[8 * p + l];
    }
    for (size_t i = idx0; i < (size_t)BS * HIDDEN; i += stride) {
        g_hh[0][i] = __ushort_as_half((unsigned short)0);
        g_hl[0][i] = __ushort_as_half((unsigned short)0);
    }
}

// ---------------- xu: fused embed-gather fp16 mma GEMM, 8 seq positions per CTA ----------------
__global__ void __launch_bounds__(512) xu_kernel(const int* __restrict__ text,
                                                 const float* __restrict__ embed)
{
    extern __shared__ __align__(16) char sm[];
    unsigned* UH = (unsigned*)(sm + X_UH);
    unsigned* UL = (unsigned*)(sm + X_UL);
    __half*   XH = (__half*)(sm + X_XH);
    __half*   XL = (__half*)(sm + X_XL);
    int*      rows = (int*)(sm + X_ROWS);

    const int jpT = blockIdx.x;
    const int tid = threadIdx.x;

    // load U packs once
    {
        const uint4* sh = (const uint4*)(g_Uh + (size_t)jpT * PACKU);
        const uint4* sl = (const uint4*)(g_Ul + (size_t)jpT * PACKU);
        uint4* dh = (uint4*)UH;
        uint4* dl = (uint4*)UL;
        for (int i = tid; i < PACKU / 4; i += 512) { dh[i] = __ldg(sh + i); dl[i] = __ldg(sl + i); }
    }

    const int w = tid >> 5, lane = tid & 31;
    const int mtq = w & 3, btile = w >> 2;
    const int g8 = lane >> 2, tig = lane & 3;
    const int hbase = (btile * 16 + g8) * SKX + tig * 2;
    const int jp0 = jpT * 64 + mtq * 16 + g8;

    for (int ss = 0; ss < SBATCH; ss++) {
        const int s = blockIdx.y * SBATCH + ss;

        __syncthreads();   // protect rows/XH/XL from previous iteration readers
        if (tid < BS) rows[tid] = text[tid * SEQ + s];
        __syncthreads();

        for (int idx = tid; idx < BS * SKX; idx += 512) {
            int b = idx / SKX, e = idx - b * SKX;
            float v = (e < EMBED) ? __ldg(embed + (size_t)rows[b] * EMBED + e) : 0.0f;
            __half hi, lo; split16(v, hi, lo);
            XH[b * SKX + e] = hi;
            XL[b * SKX + e] = lo;
        }
        __syncthreads();

        float c1[2][4], c2a[2][4], c2b[2][4];
#pragma unroll
        for (int nt = 0; nt < 2; nt++)
#pragma unroll
            for (int j = 0; j < 4; j++) { c1[nt][j] = 0.0f; c2a[nt][j] = 0.0f; c2b[nt][j] = 0.0f; }

#pragma unroll 2
        for (int ks = 0; ks < KS_XU; ks++) {
            int tile = ks * 4 + mtq;
            uint4 ah = *(const uint4*)((const char*)UH + tile * 512 + lane * 16);
            uint4 al = *(const uint4*)((const char*)UL + tile * 512 + lane * 16);
            unsigned bh0[2], bh1[2], bl0[2], bl1[2];
#pragma unroll
            for (int nt = 0; nt < 2; nt++) {
                int hb = hbase + nt * 8 * SKX + ks * 16;
                bh0[nt] = *(const unsigned*)(XH + hb);
                bh1[nt] = *(const unsigned*)(XH + hb + 8);
                bl0[nt] = *(const unsigned*)(XL + hb);
                bl1[nt] = *(const unsigned*)(XL + hb + 8);
            }
            MMA_F16(c1[0],  ah, bh0[0], bh1[0]);
            MMA_F16(c1[1],  ah, bh0[1], bh1[1]);
            MMA_F16(c2a[0], ah, bl0[0], bl1[0]);
            MMA_F16(c2a[1], ah, bl0[1], bl1[1]);
            MMA_F16(c2b[0], al, bh0[0], bh1[0]);
            MMA_F16(c2b[1], al, bh0[1], bh1[1]);
        }

        float b0 = g_br[jp0], b1 = g_br[jp0 + 8];
#pragma unroll
        for (int nt = 0; nt < 2; nt++) {
            int col = btile * 16 + nt * 8 + tig * 2;
            float2 v0 = make_float2(
                c1[nt][0] + INV2048 * (c2a[nt][0] + c2b[nt][0]) + b0,
                c1[nt][1] + INV2048 * (c2a[nt][1] + c2b[nt][1]) + b0);
            float2 v1 = make_float2(
                c1[nt][2] + INV2048 * (c2a[nt][2] + c2b[nt][2]) + b1,
                c1[nt][3] + INV2048 * (c2a[nt][3] + c2b[nt][3]) + b1);
            __stcs((float2*)(g_xu + ((size_t)s * G4H + jp0) * BS + col), v0);
            __stcs((float2*)(g_xu + ((size_t)s * G4H + jp0 + 8) * BS + col), v1);
        }
    }
}

// ---------------- persistent recurrence (512 thr, K-split, flag barrier) ----------------
__global__ void __launch_bounds__(512, 1) rnn_kernel()
{
    extern __shared__ __align__(16) char sm[];
    float* gb = (float*)(sm + R_GB);
    float* cs = (float*)(sm + R_CS);
    __half* hstH = (__half*)(sm + R_HST);
    __half* hstL = (__half*)(sm + R_HST + 1024);

    const int p = blockIdx.x;
    const int tid = threadIdx.x;
    const int lane = tid & 31;
    const int w = tid >> 5;
    const int g8 = lane >> 2, tig = lane & 3;
    const int mt = w & 1;            // cc half
    const int nq = (w >> 1) & 3;     // b quarter
    const int kh = w >> 3;           // K-split half
    const int cc0 = mt * 16;

    // load V packs; zero cell state
    {
        const uint4* sh = (const uint4*)(g_Vh + (size_t)p * PACKV);
        const uint4* sl = (const uint4*)(g_Vl + (size_t)p * PACKV);
        uint4* dh = (uint4*)(sm + R_VH);
        uint4* dl = (uint4*)(sm + R_VL);
        for (int i = tid; i < PACKV / 4; i += 512) { dh[i] = __ldg(sh + i); dl[i] = __ldg(sl + i); }
    }
    cs[tid] = 0.0f;
    __syncthreads();

    const unsigned shH0 = (unsigned)__cvta_generic_to_shared(sm + R_HH0);
    const unsigned shH1 = (unsigned)__cvta_generic_to_shared(sm + R_HH1);
    const unsigned shL0 = (unsigned)__cvta_generic_to_shared(sm + R_HL0);
    const unsigned shL1 = (unsigned)__cvta_generic_to_shared(sm + R_HL1);
    const int hbase = ((nq * 16 + g8) * SK + tig * 2) * 2;   // bytes

    for (int t = 0; t < SEQ; t++) {
        const int hbuf = t & 1;
        const __half* srcH = g_hh[hbuf];
        const __half* srcL = g_hl[hbuf];
        const float* xup = g_xu + ((size_t)t * G4H + p * CPB) * BS;

        // issue chunk 0
        {
#pragma unroll
            for (int j = 0; j < 2; j++) {
                int idx = tid + j * 512;
                int b = idx >> 4, seg = idx & 15;
                unsigned doff = (unsigned)(b * SK + seg * 8) * 2;
                int soff = b * HIDDEN + seg * 8;
                cp16(shH0 + doff, srcH + soff);
                cp16(shL0 + doff, srcL + soff);
            }
            CP_COMMIT();
        }

        float c1[2][4], c2a[2][4], c2b[2][4];
#pragma unroll
        for (int nt = 0; nt < 2; nt++)
#pragma unroll
            for (int j = 0; j < 4; j++) { c1[nt][j] = 0.0f; c2a[nt][j] = 0.0f; c2b[nt][j] = 0.0f; }
        if (kh == 0) {
#pragma unroll
            for (int nt = 0; nt < 2; nt++) {
                int bcol = nq * 16 + nt * 8 + 2 * tig;
                float2 v0 = __ldg((const float2*)(xup + (cc0 + g8) * BS + bcol));
                float2 v1 = __ldg((const float2*)(xup + (cc0 + g8 + 8) * BS + bcol));
                c1[nt][0] = v0.x; c1[nt][1] = v0.y; c1[nt][2] = v1.x; c1[nt][3] = v1.y;
            }
        }

        for (int kci = 0; kci < 8; kci++) {
            __syncthreads();   // all warps done reading buffer about to be overwritten
            if (kci + 1 < 8) {
                unsigned dH = ((kci + 1) & 1) ? shH1 : shH0;
                unsigned dL = ((kci + 1) & 1) ? shL1 : shL0;
                int kc = (kci + 1) * 128;
#pragma unroll
                for (int j = 0; j < 2; j++) {
                    int idx = tid + j * 512;
                    int b = idx >> 4, seg = idx & 15;
                    unsigned doff = (unsigned)(b * SK + seg * 8) * 2;
                    int soff = b * HIDDEN + kc + seg * 8;
                    cp16(dH + doff, srcH + soff);
                    cp16(dL + doff, srcL + soff);
                }
                CP_COMMIT();
                CP_WAIT1();
            } else {
                CP_WAIT0();
            }
            __syncthreads();   // chunk kci visible

            const char* bufH = sm + (((kci & 1) == 0) ? R_HH0 : R_HH1);
            const char* bufL = sm + (((kci & 1) == 0) ? R_HL0 : R_HL1);
#pragma unroll
            for (int ksl = 0; ksl < 4; ksl++) {
                int kg = kci * 8 + kh * 4 + ksl;
                int tile = kg * 2 + mt;
                uint4 ah = *(const uint4*)(sm + R_VH + tile * 512 + lane * 16);
                uint4 al = *(const uint4*)(sm + R_VL + tile * 512 + lane * 16);
                unsigned bh0[2], bh1[2], bl0[2], bl1[2];
#pragma unroll
                for (int nt = 0; nt < 2; nt++) {
                    int hb = hbase + nt * 8 * SK * 2 + (kh * 4 + ksl) * 32;
                    bh0[nt] = *(const unsigned*)(bufH + hb);
                    bh1[nt] = *(const unsigned*)(bufH + hb + 16);
                    bl0[nt] = *(const unsigned*)(bufL + hb);
                    bl1[nt] = *(const unsigned*)(bufL + hb + 16);
                }
                MMA_F16(c1[0],  ah, bh0[0], bh1[0]);
                MMA_F16(c1[1],  ah, bh0[1], bh1[1]);
                MMA_F16(c2a[0], ah, bl0[0], bl1[0]);
                MMA_F16(c2a[1], ah, bl0[1], bl1[1]);
                MMA_F16(c2b[0], al, bh0[0], bh1[0]);
                MMA_F16(c2b[1], al, bh0[1], bh1[1]);
            }
        }

        // combine K-split partials through gb
        float2 va[2], vb[2];
#pragma unroll
        for (int nt = 0; nt < 2; nt++) {
            va[nt] = make_float2(c1[nt][0] + INV2048 * (c2a[nt][0] + c2b[nt][0]),
                                 c1[nt][1] + INV2048 * (c2a[nt][1] + c2b[nt][1]));
            vb[nt] = make_float2(c1[nt][2] + INV2048 * (c2a[nt][2] + c2b[nt][2]),
                                 c1[nt][3] + INV2048 * (c2a[nt][3] + c2b[nt][3]));
        }
        if (kh == 0) {
#pragma unroll
            for (int nt = 0; nt < 2; nt++) {
                int col = nq * 16 + nt * 8 + 2 * tig;
                *(float2*)&gb[(cc0 + g8) * GS + col] = va[nt];
                *(float2*)&gb[(cc0 + g8 + 8) * GS + col] = vb[nt];
            }
        }
        __syncthreads();
        if (kh == 1) {
#pragma unroll
            for (int nt = 0; nt < 2; nt++) {
                int col = nq * 16 + nt * 8 + 2 * tig;
                float2* pa = (float2*)&gb[(cc0 + g8) * GS + col];
                float2* pb = (float2*)&gb[(cc0 + g8 + 8) * GS + col];
                float2 oa = *pa, ob = *pb;
                *pa = make_float2(oa.x + va[nt].x, oa.y + va[nt].y);
                *pb = make_float2(ob.x + vb[nt].x, ob.y + vb[nt].y);
            }
        }
        __syncthreads();

        // nonlinearity + state update (512 threads = 8 l x 64 b)
        {
            int l = tid >> 6;
            int b = tid & 63;
            float xi = gb[l * GS + b];
            float xf = gb[(8 + l) * GS + b];
            float xg = gb[(16 + l) * GS + b];
            float xo = gb[(24 + l) * GS + b];
            float iv = 1.0f / (1.0f + __expf(-xi));
            float fv = 1.0f / (1.0f + __expf(-xf));
            float gv = tanhf(xg);
            float ov = 1.0f / (1.0f + __expf(-xo));
            float cv = fmaf(fv, cs[tid], iv * gv);
            cs[tid] = cv;
            float hv = ov * tanhf(cv);
            __half hi, lo; split16(hv, hi, lo);
            hstH[b * 8 + l] = hi;
            hstL[b * 8 + l] = lo;
        }
        __syncthreads();

        // vectorized h store
        {
            int obuf = (t + 1) & 1;
            if (tid < 64) {
                uint4 v = *(const uint4*)(hstH + tid * 8);
                *(uint4*)(&g_hh[obuf][tid * HIDDEN + 8 * p]) = v;
            } else if (tid < 128) {
                int b = tid - 64;
                uint4 v = *(const uint4*)(hstL + b * 8);
                *(uint4*)(&g_hl[obuf][b * HIDDEN + 8 * p]) = v;
            }
        }
        __syncthreads();

        // ---- distributed flag barrier ----
        if (tid == 0) {
            __threadfence();
            *((volatile unsigned*)&g_flags[p * 32]) = (unsigned)(t + 1);
        }
        if (tid < NBLK) {
            volatile unsigned* f = &g_flags[tid * 32];
            while (*f < (unsigned)(t + 1)) { }
        }
        __threadfence();
        __syncthreads();
    }
}

// ---------------- head ----------------
__global__ void head_kernel(const float* __restrict__ W, const float* __restrict__ bd,
                            float* __restrict__ out)
{
    int wg = (blockIdx.x * blockDim.x + threadIdx.x) >> 5;
    int lane = threadIdx.x & 31;
    if (wg >= BS * POL) return;
    int b = wg / POL, pp = wg - b * POL;
    const __half* hh = g_hh[0] + (size_t)b * HIDDEN;
    const __half* hl = g_hl[0] + (size_t)b * HIDDEN;
    float s = 0.0f;
    for (int k = lane; k < HIDDEN; k += 32) {
        float h = __half2float(hh[k]) + INV2048 * __half2float(hl[k]);
        s = fmaf(h, W[k * POL + pp], s);
    }
#pragma unroll
    for (int o = 16; o; o >>= 1) s += __shfl_xor_sync(0xFFFFFFFFu, s, o);
    if (lane == 0) out[wg] = s + bd[pp];
}

// ---------------- launch ----------------
extern "C" void kernel_launch(void* const* d_in, const int* in_sizes, int n_in,
                              void* d_out, int out_size)
{
    (void)in_sizes; (void)n_in; (void)out_size;
    const int*   text  = (const int*)d_in[0];
    const float* embed = (const float*)d_in[1];
    const float* Ui = (const float*)d_in[2],  *Uf = (const float*)d_in[3];
    const float* Uc = (const float*)d_in[4],  *Uo = (const float*)d_in[5];
    const float* Vi = (const float*)d_in[6],  *Vf = (const float*)d_in[7];
    const float* Vc = (const float*)d_in[8],  *Vo = (const float*)d_in[9];
    const float* bi = (const float*)d_in[10], *bf = (const float*)d_in[11];
    const float* bc = (const float*)d_in[12], *bo = (const float*)d_in[13];
    const float* W  = (const float*)d_in[14], *bd = (const float*)d_in[15];
    float* out = (float*)d_out;

    cudaFuncSetAttribute(rnn_kernel, cudaFuncAttributeMaxDynamicSharedMemorySize, R_TOT);
    cudaFuncSetAttribute(xu_kernel, cudaFuncAttributeMaxDynamicSharedMemorySize, X_TOT);

    // dummies so ncu (-s 5 -c 1) lands on rnn_kernel (launch #6)
    dummy_kernel<<<1, 32>>>();
    dummy_kernel<<<1, 32>>>();
    dummy_kernel<<<1, 32>>>();

    prep_kernel<<<2048, 256>>>(Vi, Vf, Vc, Vo, Ui, Uf, Uc, Uo, bi, bf, bc, bo);

    dim3 gx(G4H / 64, SEQ / SBATCH);
    xu_kernel<<<gx, 512, X_TOT>>>(text, embed);

    rnn_kernel<<<NBLK, 512, R_TOT>>>();

    head_kernel<<<24, 256>>>(W, bd, out);
}